// round 4
// baseline (speedup 1.0000x reference)
#include <cuda_runtime.h>
#include <cuda_bf16.h>
#include <float.h>
#include <stdint.h>

// ---------------------------------------------------------------------------
// MVCNN: ragged max-pool -> 3-layer MLP.
// GEMMs via mma.sync.m16n8k16 (bf16 hi/lo split, f32 acc), sm_80-portable ISA.
//   C[64, N] = act[64, 4096] @ W[4096, N]
//   3 MMAs per k-step: Ah*Wh + Al*Wh + Ah*Wl  (rel err ~2^-16)
// R4: ksplit 8/16 for occupancy; W-conversion overlapped with compute.
// ---------------------------------------------------------------------------

#define BATCH 64
#define DIM   4096
#define VIEWS 256
#define OUTN  1000

__device__ __align__(256) __nv_bfloat16 g_actH[BATCH * DIM];
__device__ __align__(256) __nv_bfloat16 g_actL[BATCH * DIM];
__device__ __align__(256) float g_part[16][DIM * BATCH];  // [ksplit][feat][batch]

// ---------------------------------------------------------------------------
// helpers
// ---------------------------------------------------------------------------
__device__ __forceinline__ uint32_t smem_u32(const void* p) {
    uint32_t a;
    asm("{ .reg .u64 t; cvta.to.shared.u64 t, %1; cvt.u32.u64 %0, t; }"
        : "=r"(a) : "l"(p));
    return a;
}
__device__ __forceinline__ void cp16(uint32_t dst, const void* src) {
    asm volatile("cp.async.cg.shared.global [%0], [%1], 16;"
                 :: "r"(dst), "l"(src));
}
__device__ __forceinline__ void cp_commit() {
    asm volatile("cp.async.commit_group;" ::: "memory");
}
template<int N> __device__ __forceinline__ void cp_wait() {
    asm volatile("cp.async.wait_group %0;" :: "n"(N) : "memory");
}
__device__ __forceinline__ void ldsm4(uint32_t* r, uint32_t a) {
    asm volatile("ldmatrix.sync.aligned.m8n8.x4.shared.b16 {%0,%1,%2,%3}, [%4];"
        : "=r"(r[0]), "=r"(r[1]), "=r"(r[2]), "=r"(r[3]) : "r"(a));
}
__device__ __forceinline__ void ldsm4t(uint32_t* r, uint32_t a) {
    asm volatile("ldmatrix.sync.aligned.m8n8.x4.trans.shared.b16 {%0,%1,%2,%3}, [%4];"
        : "=r"(r[0]), "=r"(r[1]), "=r"(r[2]), "=r"(r[3]) : "r"(a));
}
__device__ __forceinline__ void mma16816(float* c, const uint32_t* a,
                                         uint32_t b0, uint32_t b1) {
    asm volatile(
        "mma.sync.aligned.m16n8k16.row.col.f32.bf16.bf16.f32 "
        "{%0,%1,%2,%3}, {%4,%5,%6,%7}, {%8,%9}, {%0,%1,%2,%3};"
        : "+f"(c[0]), "+f"(c[1]), "+f"(c[2]), "+f"(c[3])
        : "r"(a[0]), "r"(a[1]), "r"(a[2]), "r"(a[3]), "r"(b0), "r"(b1));
}

// ---------------------------------------------------------------------------
// Ragged max-pool -> bf16 hi/lo activations  act[batch][feat]
// ---------------------------------------------------------------------------
__global__ void pool_kernel(const float* __restrict__ x,
                            const float* __restrict__ xa,
                            const int*   __restrict__ lens,
                            __nv_bfloat16* __restrict__ actH,
                            __nv_bfloat16* __restrict__ actL)
{
    int warp = (blockIdx.x * blockDim.x + threadIdx.x) >> 5;
    int lane = threadIdx.x & 31;
    if (warp >= BATCH * DIM) return;
    int b = warp >> 12;
    int d = warp & 4095;

    const float* src = (d < 2048)
        ? (x  + ((size_t)(b * 2048 + d)        ) * VIEWS)
        : (xa + ((size_t)(b * 2048 + (d - 2048))) * VIEWS);

    int len = lens[b];
    len = max(1, min(len, VIEWS));

    float m = -FLT_MAX;
    for (int v0 = lane * 4; v0 < len; v0 += 128) {
        float4 v = *reinterpret_cast<const float4*>(src + v0);
        m = fmaxf(m, v.x);
        if (v0 + 1 < len) m = fmaxf(m, v.y);
        if (v0 + 2 < len) m = fmaxf(m, v.z);
        if (v0 + 3 < len) m = fmaxf(m, v.w);
    }
    #pragma unroll
    for (int o = 16; o; o >>= 1)
        m = fmaxf(m, __shfl_xor_sync(0xffffffffu, m, o));

    if (lane == 0) {
        __nv_bfloat16 h = __float2bfloat16(m);
        actH[warp] = h;
        actL[warp] = __float2bfloat16(m - __bfloat162float(h));
    }
}

// ---------------------------------------------------------------------------
// GEMM: part[ks][feat][batch] = act[64, kchunk] @ W[kchunk, Ntile]
//   grid (N/64, KSPLIT), 128 threads; warp = 16-col n slice
//   smem: 2 stages x { WH 8K | WL 8K | AH 8K | AL 8K } XOR-swizzled
// ---------------------------------------------------------------------------
#define STAGE  32768
#define OFF_WH 0
#define OFF_WL 8192
#define OFF_AH 16384
#define OFF_AL 24576
#define GEMM_SMEM (2 * STAGE + 1024)

__global__ void __launch_bounds__(128, 4) gemm_mma(
    const float* __restrict__ W, int N,
    const __nv_bfloat16* __restrict__ actH,
    const __nv_bfloat16* __restrict__ actL,
    float* __restrict__ partBase, int kchunk)
{
    extern __shared__ char smraw[];
    const uint32_t s0 = (smem_u32(smraw) + 1023) & ~1023u;
    const int tid = threadIdx.x;
    const int warp = tid >> 5, lane = tid & 31;
    const int n0 = blockIdx.x * 64;
    const int kb = blockIdx.y * kchunk;
    float* part = partBase + (size_t)blockIdx.y * (DIM * BATCH);
    const int nst = kchunk >> 6;

    // W fp32 load mapping: thread -> (k row, 32-col half)
    const int wk = tid >> 1;
    const int wn = (tid & 1) * 32;
    const float* wgp = W + (size_t)(kb + wk) * N + n0 + wn;
    const uint32_t wswz = (uint32_t)(wk & 7) << 4;
    const uint32_t wsrow = (uint32_t)wk * 128;

    // A cp.async mapping
    const int am = tid >> 1;
    const int ak = (tid & 1) * 32;
    const __nv_bfloat16* agpH = actH + (size_t)am * DIM + kb + ak;
    const __nv_bfloat16* agpL = actL + (size_t)am * DIM + kb + ak;
    uint32_t aoffc[4];
    #pragma unroll
    for (int c = 0; c < 4; ++c)
        aoffc[c] = (uint32_t)am * 128 + ((uint32_t)((ak + c * 8) * 2) ^ ((uint32_t)(am & 7) << 4));

    // ldmatrix A: lane -> row in m16, k-half
    const uint32_t arow = (lane & 7) + ((lane >> 3) & 1) * 8;
    const uint32_t ak2  = ((lane >> 4) & 1) * 16;
    const uint32_t aswz = (uint32_t)(lane & 7) << 4;
    const uint32_t aoff = arow * 128;

    // ldmatrix B trans: lane -> k row, warp n slice
    const uint32_t brow = (lane & 7) + ((lane >> 3) & 1) * 8;
    const uint32_t bn2  = (uint32_t)((warp * 16 + ((lane >> 4) & 1) * 8) * 2)
                        ^ ((uint32_t)(lane & 7) << 4);
    const uint32_t boff = brow * 128 + bn2;

    float acc[4][2][4];
    #pragma unroll
    for (int i = 0; i < 4; ++i)
        #pragma unroll
        for (int j = 0; j < 2; ++j)
            #pragma unroll
            for (int q = 0; q < 4; ++q) acc[i][j][q] = 0.f;

    float4 wreg[8];

    auto loadW = [&](int s) {
        const float* p = wgp + (size_t)s * 64 * N;
        #pragma unroll
        for (int j = 0; j < 8; ++j) {
            int col = n0 + wn + j * 4;
            if (col + 3 < N) {
                wreg[j] = *reinterpret_cast<const float4*>(p + j * 4);
            } else {
                float4 v;
                v.x = (col + 0 < N) ? p[j * 4 + 0] : 0.f;
                v.y = (col + 1 < N) ? p[j * 4 + 1] : 0.f;
                v.z = (col + 2 < N) ? p[j * 4 + 2] : 0.f;
                v.w = (col + 3 < N) ? p[j * 4 + 3] : 0.f;
                wreg[j] = v;
            }
        }
    };
    auto storeW = [&](int buf) {
        const uint32_t base = s0 + buf * STAGE + wsrow;
        #pragma unroll
        for (int j = 0; j < 8; ++j) {
            uint32_t off = ((uint32_t)((wn + j * 4) * 2)) ^ wswz;
            float4 f = wreg[j];
            uint32_t h01, h23, l01, l23;
            asm("cvt.rn.satfinite.bf16x2.f32 %0, %1, %2;" : "=r"(h01) : "f"(f.y), "f"(f.x));
            asm("cvt.rn.satfinite.bf16x2.f32 %0, %1, %2;" : "=r"(h23) : "f"(f.w), "f"(f.z));
            float l0 = f.x - __uint_as_float(h01 << 16);
            float l1 = f.y - __uint_as_float(h01 & 0xffff0000u);
            float l2 = f.z - __uint_as_float(h23 << 16);
            float l3 = f.w - __uint_as_float(h23 & 0xffff0000u);
            asm("cvt.rn.satfinite.bf16x2.f32 %0, %1, %2;" : "=r"(l01) : "f"(l1), "f"(l0));
            asm("cvt.rn.satfinite.bf16x2.f32 %0, %1, %2;" : "=r"(l23) : "f"(l3), "f"(l2));
            asm volatile("st.shared.v2.b32 [%0], {%1,%2};"
                         :: "r"(base + OFF_WH + off), "r"(h01), "r"(h23));
            asm volatile("st.shared.v2.b32 [%0], {%1,%2};"
                         :: "r"(base + OFF_WL + off), "r"(l01), "r"(l23));
        }
    };
    auto issueA = [&](int s, int buf) {
        const uint32_t base = s0 + buf * STAGE;
        #pragma unroll
        for (int c = 0; c < 4; ++c) {
            cp16(base + OFF_AH + aoffc[c], agpH + s * 64 + c * 8);
            cp16(base + OFF_AL + aoffc[c], agpL + s * 64 + c * 8);
        }
        cp_commit();
    };
    auto compute = [&](int buf) {
        const uint32_t base = s0 + buf * STAGE;
        #pragma unroll
        for (int ks = 0; ks < 4; ++ks) {
            uint32_t bh[4], bl[4];
            ldsm4t(bh, base + OFF_WH + ks * 2048 + boff);
            ldsm4t(bl, base + OFF_WL + ks * 2048 + boff);
            const uint32_t kx = (uint32_t)(ks * 32 + ak2) ^ aswz;
            #pragma unroll
            for (int mt = 0; mt < 4; ++mt) {
                uint32_t ah[4], al[4];
                ldsm4(ah, base + OFF_AH + mt * 2048 + aoff + kx);
                ldsm4(al, base + OFF_AL + mt * 2048 + aoff + kx);
                mma16816(acc[mt][0], ah, bh[0], bh[1]);
                mma16816(acc[mt][1], ah, bh[2], bh[3]);
                mma16816(acc[mt][0], al, bh[0], bh[1]);
                mma16816(acc[mt][1], al, bh[2], bh[3]);
                mma16816(acc[mt][0], ah, bl[0], bl[1]);
                mma16816(acc[mt][1], ah, bl[2], bl[3]);
            }
        }
    };

    // ---- software pipeline: W conversion for s+1 overlaps compute(s) ----
    issueA(0, 0);
    loadW(0);
    storeW(0);
    if (nst > 1) loadW(1);
    cp_wait<0>();
    __syncthreads();

    for (int s = 0; s < nst; ++s) {
        const int buf = s & 1;
        if (s + 1 < nst) {
            issueA(s + 1, buf ^ 1);    // A(s+1) -> other buffer (cp.async)
            storeW(buf ^ 1);           // convert W(s+1), overlaps MMA across warps
            if (s + 2 < nst) loadW(s + 2);  // LDG for s+2, latency under compute
        }
        compute(buf);
        cp_wait<0>();
        __syncthreads();
    }

    // epilogue: scatter f32 partials  part[feat*64 + batch]
    const int g = lane >> 2, tg = lane & 3;
    #pragma unroll
    for (int mt = 0; mt < 4; ++mt)
        #pragma unroll
        for (int nt = 0; nt < 2; ++nt) {
            int feat = n0 + warp * 16 + nt * 8 + tg * 2;
            int bat  = mt * 16 + g;
            float* p = part + (size_t)feat * 64 + bat;
            p[0]      = acc[mt][nt][0];
            p[64]     = acc[mt][nt][1];
            p[8]      = acc[mt][nt][2];
            p[64 + 8] = acc[mt][nt][3];
        }
}

// ---------------------------------------------------------------------------
// Reduce K-splits + bias + relu -> next-layer bf16 hi/lo activations
// ---------------------------------------------------------------------------
__global__ void reduce_bias_relu(const float* __restrict__ bias,
                                 __nv_bfloat16* __restrict__ actH,
                                 __nv_bfloat16* __restrict__ actL)
{
    int idx = blockIdx.x * 256 + threadIdx.x;   // 64*4096
    int n = idx >> 12;       // batch
    int m = idx & 4095;      // feat
    float s = bias[m];
    #pragma unroll
    for (int z = 0; z < 8; ++z) s += g_part[z][m * 64 + n];
    s = fmaxf(s, 0.f);
    __nv_bfloat16 h = __float2bfloat16(s);
    actH[idx] = h;
    actL[idx] = __float2bfloat16(s - __bfloat162float(h));
}

__global__ void reduce_out(const float* __restrict__ b3,
                           float* __restrict__ out)
{
    int idx = blockIdx.x * 256 + threadIdx.x;
    if (idx >= BATCH * OUTN) return;
    int n = idx / OUTN;      // batch
    int m = idx - n * OUTN;  // feat
    float s = b3[m];
    #pragma unroll
    for (int z = 0; z < 16; ++z) s += g_part[z][m * 64 + n];
    out[idx] = s;
}

// ---------------------------------------------------------------------------
// launch
// ---------------------------------------------------------------------------
extern "C" void kernel_launch(void* const* d_in, const int* in_sizes, int n_in,
                              void* d_out, int out_size)
{
    const float* x    = (const float*)d_in[0];
    const float* xa   = (const float*)d_in[1];
    const int*   lens = (const int*)  d_in[2];
    const float* w1   = (const float*)d_in[3];
    const float* b1   = (const float*)d_in[4];
    const float* w2   = (const float*)d_in[5];
    const float* b2   = (const float*)d_in[6];
    const float* w3   = (const float*)d_in[7];
    const float* b3   = (const float*)d_in[8];
    float* out = (float*)d_out;

    __nv_bfloat16 *actH, *actL;
    float* part;
    cudaGetSymbolAddress((void**)&actH, g_actH);
    cudaGetSymbolAddress((void**)&actL, g_actL);
    cudaGetSymbolAddress((void**)&part, g_part);

    cudaFuncSetAttribute(gemm_mma, cudaFuncAttributeMaxDynamicSharedMemorySize,
                         GEMM_SMEM);

    // 1) pool -> act hi/lo
    {
        int warps = BATCH * DIM;
        int blocks = (warps * 32 + 255) / 256;
        pool_kernel<<<blocks, 256>>>(x, xa, lens, actH, actL);
    }
    // 2) layer 1: ksplit 8, kchunk 512
    gemm_mma<<<dim3(64, 8), 128, GEMM_SMEM>>>(w1, DIM, actH, actL, part, 512);
    reduce_bias_relu<<<1024, 256>>>(b1, actH, actL);
    // 3) layer 2
    gemm_mma<<<dim3(64, 8), 128, GEMM_SMEM>>>(w2, DIM, actH, actL, part, 512);
    reduce_bias_relu<<<1024, 256>>>(b2, actH, actL);
    // 4) layer 3: N=1000, ksplit 16, kchunk 256
    gemm_mma<<<dim3(16, 16), 128, GEMM_SMEM>>>(w3, OUTN, actH, actL, part, 256);
    reduce_out<<<(BATCH * OUTN + 255) / 256, 256>>>(b3, out);
}

// round 5
// speedup vs baseline: 1.3846x; 1.3846x over previous
#include <cuda_runtime.h>
#include <cuda_bf16.h>
#include <float.h>
#include <stdint.h>

// ---------------------------------------------------------------------------
// MVCNN: ragged max-pool -> 3-layer MLP.
// GEMMs via mma.sync.m16n8k16 (bf16 hi/lo split, f32 acc), sm_80-portable ISA.
//   C[64, N] = act[64, 4096] @ W[4096, N]
//   3 MMAs per k-step: Ah*Wh + Al*Wh + Ah*Wl  (rel err ~2^-16)
// R5: CTA tile n128 x m64, 8 warps (2m x 4n, warp m32 x n32) -> less smem
//     traffic per output; R3-proven pipeline ordering; ksplit 8/16.
// ---------------------------------------------------------------------------

#define BATCH 64
#define DIM   4096
#define VIEWS 256
#define OUTN  1000

__device__ __align__(256) __nv_bfloat16 g_actH[BATCH * DIM];
__device__ __align__(256) __nv_bfloat16 g_actL[BATCH * DIM];
__device__ __align__(256) float g_part[16][DIM * BATCH];  // [ksplit][feat][batch]

// ---------------------------------------------------------------------------
// helpers
// ---------------------------------------------------------------------------
__device__ __forceinline__ uint32_t smem_u32(const void* p) {
    uint32_t a;
    asm("{ .reg .u64 t; cvta.to.shared.u64 t, %1; cvt.u32.u64 %0, t; }"
        : "=r"(a) : "l"(p));
    return a;
}
__device__ __forceinline__ void cp16(uint32_t dst, const void* src) {
    asm volatile("cp.async.cg.shared.global [%0], [%1], 16;"
                 :: "r"(dst), "l"(src));
}
__device__ __forceinline__ void cp_commit() {
    asm volatile("cp.async.commit_group;" ::: "memory");
}
template<int N> __device__ __forceinline__ void cp_wait() {
    asm volatile("cp.async.wait_group %0;" :: "n"(N) : "memory");
}
__device__ __forceinline__ void ldsm4(uint32_t* r, uint32_t a) {
    asm volatile("ldmatrix.sync.aligned.m8n8.x4.shared.b16 {%0,%1,%2,%3}, [%4];"
        : "=r"(r[0]), "=r"(r[1]), "=r"(r[2]), "=r"(r[3]) : "r"(a));
}
__device__ __forceinline__ void ldsm4t(uint32_t* r, uint32_t a) {
    asm volatile("ldmatrix.sync.aligned.m8n8.x4.trans.shared.b16 {%0,%1,%2,%3}, [%4];"
        : "=r"(r[0]), "=r"(r[1]), "=r"(r[2]), "=r"(r[3]) : "r"(a));
}
__device__ __forceinline__ void mma16816(float* c, const uint32_t* a,
                                         uint32_t b0, uint32_t b1) {
    asm volatile(
        "mma.sync.aligned.m16n8k16.row.col.f32.bf16.bf16.f32 "
        "{%0,%1,%2,%3}, {%4,%5,%6,%7}, {%8,%9}, {%0,%1,%2,%3};"
        : "+f"(c[0]), "+f"(c[1]), "+f"(c[2]), "+f"(c[3])
        : "r"(a[0]), "r"(a[1]), "r"(a[2]), "r"(a[3]), "r"(b0), "r"(b1));
}

// ---------------------------------------------------------------------------
// Ragged max-pool -> bf16 hi/lo activations  act[batch][feat]
// ---------------------------------------------------------------------------
__global__ void pool_kernel(const float* __restrict__ x,
                            const float* __restrict__ xa,
                            const int*   __restrict__ lens,
                            __nv_bfloat16* __restrict__ actH,
                            __nv_bfloat16* __restrict__ actL)
{
    int warp = (blockIdx.x * blockDim.x + threadIdx.x) >> 5;
    int lane = threadIdx.x & 31;
    if (warp >= BATCH * DIM) return;
    int b = warp >> 12;
    int d = warp & 4095;

    const float* src = (d < 2048)
        ? (x  + ((size_t)(b * 2048 + d)        ) * VIEWS)
        : (xa + ((size_t)(b * 2048 + (d - 2048))) * VIEWS);

    int len = lens[b];
    len = max(1, min(len, VIEWS));

    float m = -FLT_MAX;
    for (int v0 = lane * 4; v0 < len; v0 += 128) {
        float4 v = *reinterpret_cast<const float4*>(src + v0);
        m = fmaxf(m, v.x);
        if (v0 + 1 < len) m = fmaxf(m, v.y);
        if (v0 + 2 < len) m = fmaxf(m, v.z);
        if (v0 + 3 < len) m = fmaxf(m, v.w);
    }
    #pragma unroll
    for (int o = 16; o; o >>= 1)
        m = fmaxf(m, __shfl_xor_sync(0xffffffffu, m, o));

    if (lane == 0) {
        __nv_bfloat16 h = __float2bfloat16(m);
        actH[warp] = h;
        actL[warp] = __float2bfloat16(m - __bfloat162float(h));
    }
}

// ---------------------------------------------------------------------------
// GEMM: part[ks][feat][batch] = act[64, kchunk] @ W[kchunk, n128-tile]
//   grid (ceil(N/128), KSPLIT), 256 threads = 8 warps, warp tile m32 x n32
//   smem: 2 stages x { WH 16K (k64 x n128) | WL 16K | AH 8K | AL 8K }
// ---------------------------------------------------------------------------
#define STAGE  49152
#define OFF_WH 0
#define OFF_WL 16384
#define OFF_AH 32768
#define OFF_AL 40960
#define GEMM_SMEM (2 * STAGE + 1024)

__global__ void __launch_bounds__(256) gemm_mma(
    const float* __restrict__ W, int N,
    const __nv_bfloat16* __restrict__ actH,
    const __nv_bfloat16* __restrict__ actL,
    float* __restrict__ partBase, int kchunk)
{
    extern __shared__ char smraw[];
    const uint32_t s0 = (smem_u32(smraw) + 1023) & ~1023u;
    const int tid = threadIdx.x;
    const int warp = tid >> 5, lane = tid & 31;
    const int warpM = warp & 1;         // m32 slice of batch-64
    const int warpN = warp >> 1;        // n32 slice of 128
    const int n0 = blockIdx.x * 128;
    const int kb = blockIdx.y * kchunk;
    float* part = partBase + (size_t)blockIdx.y * (DIM * BATCH);
    const int nst = kchunk >> 6;

    // W fp32 load: thread -> k row (tid>>2), n quarter ((tid&3)*32); 8 float4
    const int wk = tid >> 2;
    const int wn = (tid & 3) * 32;
    const float* wgp = W + (size_t)(kb + wk) * N + n0 + wn;
    const uint32_t wswz = (uint32_t)(wk & 7) << 4;
    const uint32_t wsrow = (uint32_t)wk * 256;

    // A cp.async: thread -> m row (tid>>2), k chunk; 2 x 16B per polarity
    const int am = tid >> 2;
    const int akb = (tid & 3) * 16;                 // k elem offset
    const __nv_bfloat16* agpH = actH + (size_t)am * DIM + kb + akb;
    const __nv_bfloat16* agpL = actL + (size_t)am * DIM + kb + akb;
    uint32_t aoffc[2];
    #pragma unroll
    for (int c = 0; c < 2; ++c)
        aoffc[c] = (uint32_t)am * 128
                 + (((uint32_t)(akb * 2 + c * 16)) ^ ((uint32_t)(am & 7) << 4));

    // ldmatrix A: lane -> row within m16 tile, k-half
    const uint32_t arow = (lane & 7) + ((lane >> 3) & 1) * 8;
    const uint32_t ak2  = ((lane >> 4) & 1) * 16;   // byte offset (k8)
    const uint32_t aswz = (uint32_t)(lane & 7) << 4;

    // ldmatrix B trans on W smem [k][n128]: lane -> k row; n via warpN/nt
    const uint32_t brow  = (lane & 7) + ((lane >> 3) & 1) * 8;
    const uint32_t bhalf = ((lane >> 4) & 1) * 8;   // n elems

    float acc[2][4][4];
    #pragma unroll
    for (int i = 0; i < 2; ++i)
        #pragma unroll
        for (int j = 0; j < 4; ++j)
            #pragma unroll
            for (int q = 0; q < 4; ++q) acc[i][j][q] = 0.f;

    float4 wreg[8];

    auto loadW = [&](int s) {
        const float* p = wgp + (size_t)s * 64 * N;
        #pragma unroll
        for (int j = 0; j < 8; ++j) {
            int col = n0 + wn + j * 4;
            if (col + 3 < N) {
                wreg[j] = *reinterpret_cast<const float4*>(p + j * 4);
            } else {
                float4 v;
                v.x = (col + 0 < N) ? p[j * 4 + 0] : 0.f;
                v.y = (col + 1 < N) ? p[j * 4 + 1] : 0.f;
                v.z = (col + 2 < N) ? p[j * 4 + 2] : 0.f;
                v.w = (col + 3 < N) ? p[j * 4 + 3] : 0.f;
                wreg[j] = v;
            }
        }
    };
    auto storeW = [&](int buf) {
        const uint32_t base = s0 + buf * STAGE + wsrow;
        #pragma unroll
        for (int j = 0; j < 8; ++j) {
            uint32_t off = ((uint32_t)((wn + j * 4) * 2)) ^ wswz;
            float4 f = wreg[j];
            uint32_t h01, h23, l01, l23;
            asm("cvt.rn.satfinite.bf16x2.f32 %0, %1, %2;" : "=r"(h01) : "f"(f.y), "f"(f.x));
            asm("cvt.rn.satfinite.bf16x2.f32 %0, %1, %2;" : "=r"(h23) : "f"(f.w), "f"(f.z));
            float l0 = f.x - __uint_as_float(h01 << 16);
            float l1 = f.y - __uint_as_float(h01 & 0xffff0000u);
            float l2 = f.z - __uint_as_float(h23 << 16);
            float l3 = f.w - __uint_as_float(h23 & 0xffff0000u);
            asm("cvt.rn.satfinite.bf16x2.f32 %0, %1, %2;" : "=r"(l01) : "f"(l1), "f"(l0));
            asm("cvt.rn.satfinite.bf16x2.f32 %0, %1, %2;" : "=r"(l23) : "f"(l3), "f"(l2));
            asm volatile("st.shared.v2.b32 [%0], {%1,%2};"
                         :: "r"(base + OFF_WH + off), "r"(h01), "r"(h23));
            asm volatile("st.shared.v2.b32 [%0], {%1,%2};"
                         :: "r"(base + OFF_WL + off), "r"(l01), "r"(l23));
        }
    };
    auto issueA = [&](int s, int buf) {
        const uint32_t base = s0 + buf * STAGE;
        #pragma unroll
        for (int c = 0; c < 2; ++c) {
            cp16(base + OFF_AH + aoffc[c], agpH + s * 64 + c * 8);
            cp16(base + OFF_AL + aoffc[c], agpL + s * 64 + c * 8);
        }
        cp_commit();
    };
    auto compute = [&](int buf) {
        const uint32_t base = s0 + buf * STAGE;
        #pragma unroll
        for (int ks = 0; ks < 4; ++ks) {
            // B: n32 slice = 2 x n16, hi and lo
            uint32_t bh[2][4], bl[2][4];
            #pragma unroll
            for (int nt = 0; nt < 2; ++nt) {
                uint32_t bcol = ((uint32_t)((warpN * 32 + nt * 16 + bhalf) * 2))
                              ^ ((uint32_t)(lane & 7) << 4);
                uint32_t boff = (uint32_t)(ks * 16 + brow) * 256 + bcol;
                ldsm4t(bh[nt], base + OFF_WH + boff);
                ldsm4t(bl[nt], base + OFF_WL + boff);
            }
            const uint32_t kx = (uint32_t)(ks * 32 + ak2) ^ aswz;
            #pragma unroll
            for (int mt = 0; mt < 2; ++mt) {
                const uint32_t arow0 = (uint32_t)(warpM * 32 + mt * 16) * 128
                                     + arow * 128 + kx;
                uint32_t ah[4], al[4];
                ldsm4(ah, base + OFF_AH + arow0);
                ldsm4(al, base + OFF_AL + arow0);
                #pragma unroll
                for (int nt = 0; nt < 2; ++nt) {
                    mma16816(acc[mt][nt * 2 + 0], ah, bh[nt][0], bh[nt][1]);
                    mma16816(acc[mt][nt * 2 + 1], ah, bh[nt][2], bh[nt][3]);
                    mma16816(acc[mt][nt * 2 + 0], al, bh[nt][0], bh[nt][1]);
                    mma16816(acc[mt][nt * 2 + 1], al, bh[nt][2], bh[nt][3]);
                    mma16816(acc[mt][nt * 2 + 0], ah, bl[nt][0], bl[nt][1]);
                    mma16816(acc[mt][nt * 2 + 1], ah, bl[nt][2], bl[nt][3]);
                }
            }
        }
    };

    // ---- R3-proven pipeline ordering ----
    issueA(0, 0);
    loadW(0);
    for (int s = 0; s < nst; ++s) {
        const int buf = s & 1;
        storeW(buf);
        if (s + 1 < nst) {
            issueA(s + 1, buf ^ 1);
            loadW(s + 1);
            cp_wait<1>();
        } else {
            cp_wait<0>();
        }
        __syncthreads();
        compute(buf);
        __syncthreads();
    }

    // epilogue: scatter f32 partials  part[feat*64 + batch]
    const int g = lane >> 2, tg = lane & 3;
    #pragma unroll
    for (int mt = 0; mt < 2; ++mt)
        #pragma unroll
        for (int nt = 0; nt < 4; ++nt) {
            int feat = n0 + warpN * 32 + nt * 8 + tg * 2;
            int bat  = warpM * 32 + mt * 16 + g;
            float* p = part + (size_t)feat * 64 + bat;
            p[0]      = acc[mt][nt][0];
            p[64]     = acc[mt][nt][1];
            p[8]      = acc[mt][nt][2];
            p[64 + 8] = acc[mt][nt][3];
        }
}

// ---------------------------------------------------------------------------
// Reduce K-splits + bias + relu -> next-layer bf16 hi/lo activations
// ---------------------------------------------------------------------------
__global__ void reduce_bias_relu(const float* __restrict__ bias,
                                 __nv_bfloat16* __restrict__ actH,
                                 __nv_bfloat16* __restrict__ actL)
{
    int idx = blockIdx.x * 256 + threadIdx.x;   // 64*4096
    int n = idx >> 12;       // batch
    int m = idx & 4095;      // feat
    float s = bias[m];
    #pragma unroll
    for (int z = 0; z < 8; ++z) s += g_part[z][m * 64 + n];
    s = fmaxf(s, 0.f);
    __nv_bfloat16 h = __float2bfloat16(s);
    actH[idx] = h;
    actL[idx] = __float2bfloat16(s - __bfloat162float(h));
}

__global__ void reduce_out(const float* __restrict__ b3,
                           float* __restrict__ out)
{
    int idx = blockIdx.x * 256 + threadIdx.x;
    if (idx >= BATCH * OUTN) return;
    int n = idx / OUTN;      // batch
    int m = idx - n * OUTN;  // feat
    float s = b3[m];
    #pragma unroll
    for (int z = 0; z < 16; ++z) s += g_part[z][m * 64 + n];
    out[idx] = s;
}

// ---------------------------------------------------------------------------
// launch
// ---------------------------------------------------------------------------
extern "C" void kernel_launch(void* const* d_in, const int* in_sizes, int n_in,
                              void* d_out, int out_size)
{
    const float* x    = (const float*)d_in[0];
    const float* xa   = (const float*)d_in[1];
    const int*   lens = (const int*)  d_in[2];
    const float* w1   = (const float*)d_in[3];
    const float* b1   = (const float*)d_in[4];
    const float* w2   = (const float*)d_in[5];
    const float* b2   = (const float*)d_in[6];
    const float* w3   = (const float*)d_in[7];
    const float* b3   = (const float*)d_in[8];
    float* out = (float*)d_out;

    __nv_bfloat16 *actH, *actL;
    float* part;
    cudaGetSymbolAddress((void**)&actH, g_actH);
    cudaGetSymbolAddress((void**)&actL, g_actL);
    cudaGetSymbolAddress((void**)&part, g_part);

    cudaFuncSetAttribute(gemm_mma, cudaFuncAttributeMaxDynamicSharedMemorySize,
                         GEMM_SMEM);

    // 1) pool -> act hi/lo
    {
        int warps = BATCH * DIM;
        int blocks = (warps * 32 + 255) / 256;
        pool_kernel<<<blocks, 256>>>(x, xa, lens, actH, actL);
    }
    // 2) layer 1: n-tiles 32, ksplit 8 (kchunk 512, 8 stages)
    gemm_mma<<<dim3(32, 8), 256, GEMM_SMEM>>>(w1, DIM, actH, actL, part, 512);
    reduce_bias_relu<<<1024, 256>>>(b1, actH, actL);
    // 3) layer 2
    gemm_mma<<<dim3(32, 8), 256, GEMM_SMEM>>>(w2, DIM, actH, actL, part, 512);
    reduce_bias_relu<<<1024, 256>>>(b2, actH, actL);
    // 4) layer 3: N=1000 -> 8 n-tiles, ksplit 16 (kchunk 256, 4 stages)
    gemm_mma<<<dim3(8, 16), 256, GEMM_SMEM>>>(w3, OUTN, actH, actL, part, 256);
    reduce_out<<<(BATCH * OUTN + 255) / 256, 256>>>(b3, out);
}